// round 15
// baseline (speedup 1.0000x reference)
#include <cuda_runtime.h>
#include <cuda_bf16.h>
#include <cuda_fp16.h>
#include <cstdint>

// Problem shape (fixed for this dataset variant)
#define NNODES 50000
#define NEDGES 800000
#define IN_DIM 256
#define KHEADS 4
#define FDIM   64
#define KF     256   // KHEADS * FDIM == IN_DIM here

// Scratch (device globals: allocation-free per harness rules)
__device__ __half  g_nodefeat_h[(size_t)NNODES * KF];  // [N, 256] fp16
__device__ uint2   g_gauss_h[NEDGES];                  // [E, 4] fp16 weights
__device__ __half  g_w_h[KF * IN_DIM];                 // W fp16

// ===========================================================================
// Helpers (family-common PTX only: ldmatrix + mma.sync, no tcgen05)
// ===========================================================================
__device__ __forceinline__ uint32_t smem_to_u32(const void* p) {
    uint32_t a;
    asm("{ .reg .u64 t; cvta.to.shared.u64 t, %1; cvt.u32.u64 %0, t; }"
        : "=r"(a) : "l"(p));
    return a;
}

__device__ __forceinline__ void ldmatrix_x4(uint32_t* r, uint32_t addr) {
    asm volatile("ldmatrix.sync.aligned.m8n8.x4.shared.b16 {%0,%1,%2,%3}, [%4];"
        : "=r"(r[0]), "=r"(r[1]), "=r"(r[2]), "=r"(r[3]) : "r"(addr));
}

__device__ __forceinline__ void mma_f16(float* d, const uint32_t* a,
                                        uint32_t b0, uint32_t b1) {
    asm volatile(
        "mma.sync.aligned.m16n8k16.row.col.f32.f16.f16.f32 "
        "{%0,%1,%2,%3}, {%4,%5,%6,%7}, {%8,%9}, {%0,%1,%2,%3};"
        : "+f"(d[0]), "+f"(d[1]), "+f"(d[2]), "+f"(d[3])
        : "r"(a[0]), "r"(a[1]), "r"(a[2]), "r"(a[3]), "r"(b0), "r"(b1));
}

__device__ __forceinline__ uint32_t pack2h(__half x, __half y) {
    uint16_t lo = *(uint16_t*)&x, hi = *(uint16_t*)&y;
    return (uint32_t)lo | ((uint32_t)hi << 16);
}

// ===========================================================================
// Kernel P: fused prep — gaussian weights for all edges + W fp32->fp16.
// Launched before the GEMM; both outputs are consumed downstream only.
// ===========================================================================
__global__ void prep_kernel(const float* __restrict__ W,
                            const float* __restrict__ pseudo,
                            const float* __restrict__ mu,
                            const float* __restrict__ inv_sigma,
                            int E)
{
    const int i = blockIdx.x * blockDim.x + threadIdx.x;

    // W conversion: first 16384 threads (64 blocks), 1 float4 each
    if (i < (KF * IN_DIM) / 4) {
        const float4 v = ((const float4*)W)[i];
        ((uint2*)g_w_h)[i] = make_uint2(
            pack2h(__float2half_rn(v.x), __float2half_rn(v.y)),
            pack2h(__float2half_rn(v.z), __float2half_rn(v.w)));
    }

    // gaussian weights: one edge per thread
    if (i < E) {
        const float2 p = *(const float2*)(pseudo + 2 * (size_t)i);
        float w[4];
#pragma unroll
        for (int k = 0; k < 4; k++) {
            const float dx = p.x - mu[2 * k + 0];
            const float dy = p.y - mu[2 * k + 1];
            const float sx = inv_sigma[2 * k + 0];
            const float sy = inv_sigma[2 * k + 1];
            const float t  = dx * dx * sx * sx + dy * dy * sy * sy;
            w[k] = expf(-0.5f * t);
        }
        g_gauss_h[i] = make_uint2(
            pack2h(__float2half_rn(w[0]), __float2half_rn(w[1])),
            pack2h(__float2half_rn(w[2]), __float2half_rn(w[3])));
    }
}

// ===========================================================================
// Kernel A: fp16 tensor-core GEMM, software-pipelined (exact R12/R13 version).
// ===========================================================================
#define BK2     32
#define A_ROW_B 80                      // 32 fp16 + 8 pad (bytes)
#define A_BUF_B (128 * A_ROW_B)         // 10240
#define W_ROW_B 528                     // 256 fp16 + 8 pad (bytes)
#define W_BUF_B (128 * W_ROW_B)         // 67584
#define GEMM_SMEM (2 * A_BUF_B + W_BUF_B)   // 88064

__global__ __launch_bounds__(256, 2)
void gemm_mma_kernel(const float* __restrict__ A, __half* __restrict__ C, int M)
{
    extern __shared__ char smem[];
    const uint32_t sb  = smem_to_u32(smem);
    const uint32_t sW  = sb + 2 * A_BUF_B;

    const int tid  = threadIdx.x;
    const int wid  = tid >> 5;
    const int lane = tid & 31;
    const int m0   = blockIdx.x * 128;
    const int bn   = blockIdx.y * 128;

    const int wm = wid & 1;      // m half (64)
    const int wn = wid >> 1;     // n quarter (32)

    // ---- prologue: W tile 128x256 fp16 -> smem (once) ----
#pragma unroll
    for (int j = 0; j < 16; j++) {
        const int id  = tid + j * 256;     // 0..4095
        const int row = id >> 5;           // 0..127
        const int c8  = (id & 31) * 8;     // fp16 col
        const uint4 w = *(const uint4*)(g_w_h + (size_t)(bn + row) * IN_DIM + c8);
        *(uint4*)(smem + 2 * A_BUF_B + row * W_ROW_B + c8 * 2) = w;
    }

    float acc[4][4][4];
#pragma unroll
    for (int i = 0; i < 4; i++)
#pragma unroll
        for (int j = 0; j < 4; j++)
#pragma unroll
            for (int q = 0; q < 4; q++) acc[i][j][q] = 0.0f;

    float4 pref[4];
#pragma unroll
    for (int j = 0; j < 4; j++) {               // prefetch chunk 0
        const int id  = tid + j * 256;
        const int row = id >> 3;
        const int c4  = (id & 7) * 4;
        const int gm  = m0 + row;
        pref[j] = (gm < M)
            ? *(const float4*)(A + (size_t)gm * IN_DIM + 0 * BK2 + c4)
            : make_float4(0.f, 0.f, 0.f, 0.f);
    }

    for (int c = 0; c < IN_DIM / BK2; c++) {
        const uint32_t abuf = sb + (uint32_t)(c & 1) * A_BUF_B;

        // ---- STS chunk c (convert fp32 regs -> fp16 smem) ----
#pragma unroll
        for (int j = 0; j < 4; j++) {
            const int id  = tid + j * 256;
            const int row = id >> 3;
            const int c4  = (id & 7) * 4;
            const float4 a = pref[j];
            asm volatile("st.shared.v2.b32 [%0], {%1,%2};" ::
                "r"(abuf + (uint32_t)(row * A_ROW_B + c4 * 2)),
                "r"(pack2h(__float2half_rn(a.x), __float2half_rn(a.y))),
                "r"(pack2h(__float2half_rn(a.z), __float2half_rn(a.w))) : "memory");
        }
        // ---- prefetch chunk c+1 (overlaps with compute below) ----
        if (c < IN_DIM / BK2 - 1) {
#pragma unroll
            for (int j = 0; j < 4; j++) {
                const int id  = tid + j * 256;
                const int row = id >> 3;
                const int c4  = (id & 7) * 4;
                const int gm  = m0 + row;
                pref[j] = (gm < M)
                    ? *(const float4*)(A + (size_t)gm * IN_DIM + (c + 1) * BK2 + c4)
                    : make_float4(0.f, 0.f, 0.f, 0.f);
            }
        }
        __syncthreads();

        // ---- compute chunk c: 2 k16 steps ----
#pragma unroll
        for (int ks = 0; ks < 2; ks++) {
            const uint32_t kbyte = (uint32_t)((ks * 16 + (lane >> 4) * 8) * 2);

            uint32_t af[4][4];
#pragma unroll
            for (int mt = 0; mt < 4; mt++) {
                const uint32_t roff =
                    (uint32_t)((wm * 64 + mt * 16 + (lane & 15)) * A_ROW_B) + kbyte;
                ldmatrix_x4(af[mt], abuf + roff);
            }
            uint32_t bf[2][4];
            const uint32_t wkoff = (uint32_t)(c * BK2 * 2) + kbyte;
#pragma unroll
            for (int bg = 0; bg < 2; bg++) {
                const uint32_t roff =
                    (uint32_t)((wn * 32 + bg * 16 + (lane & 15)) * W_ROW_B) + wkoff;
                ldmatrix_x4(bf[bg], sW + roff);
            }

#pragma unroll
            for (int mt = 0; mt < 4; mt++) {
#pragma unroll
                for (int nt = 0; nt < 4; nt++) {
                    const int bg = nt >> 1, sel = nt & 1;
                    mma_f16(acc[mt][nt], af[mt], bf[bg][sel], bf[bg][sel + 2]);
                }
            }
        }
    }

    // ---- epilogue: fragment -> gmem fp16 ----
    const int qrow = lane >> 2;
    const int qcol = (lane & 3) * 2;
#pragma unroll
    for (int mt = 0; mt < 4; mt++) {
        const int r0 = m0 + wm * 64 + mt * 16 + qrow;
#pragma unroll
        for (int nt = 0; nt < 4; nt++) {
            const int col = bn + wn * 32 + nt * 8 + qcol;
            if (r0 < M)
                *(__half2*)(C + (size_t)r0 * KF + col) =
                    __floats2half2_rn(acc[mt][nt][0], acc[mt][nt][1]);
            if (r0 + 8 < M)
                *(__half2*)(C + (size_t)(r0 + 8) * KF + col) =
                    __floats2half2_rn(acc[mt][nt][2], acc[mt][nt][3]);
        }
    }
}

// ---------------------------------------------------------------------------
// Kernel C: dual-row agg. One warp owns rows {2r, 2r+1}; the main loop
// processes 2 edges from EACH row per iteration (16 independent gather loads
// in flight, 4 chains) to cover gather latency. Remainders drain with the
// proven 2-edge loop. Per-edge math identical to R13 (fp16 weights).
// ---------------------------------------------------------------------------
__device__ __forceinline__ void agg_edge2(const __half* __restrict__ b,
                                          const uint2 wp, float& ax, float& ay)
{
    const float2 v0 = __half22float2(*(const __half2*)(b + 0));
    const float2 v1 = __half22float2(*(const __half2*)(b + 64));
    const float2 v2 = __half22float2(*(const __half2*)(b + 128));
    const float2 v3 = __half22float2(*(const __half2*)(b + 192));
    const float2 wa = __half22float2(*(const __half2*)&wp.x);
    const float2 wb = __half22float2(*(const __half2*)&wp.y);
    ax = fmaf(wa.x, v0.x, ax); ay = fmaf(wa.x, v0.y, ay);
    ax = fmaf(wa.y, v1.x, ax); ay = fmaf(wa.y, v1.y, ay);
    ax = fmaf(wb.x, v2.x, ax); ay = fmaf(wb.x, v2.y, ay);
    ax = fmaf(wb.y, v3.x, ax); ay = fmaf(wb.y, v3.y, ay);
}

__global__ void agg_kernel(const int* __restrict__ rowptr,
                           const int* __restrict__ colind,
                           const float* __restrict__ bias,
                           float* __restrict__ out, int N)
{
    const int warp = (blockIdx.x * blockDim.x + threadIdx.x) >> 5;
    const int lane = threadIdx.x & 31;
    const int r0 = 2 * warp;
    if (r0 >= N) return;
    const int r1 = r0 + 1;

    int e0        = rowptr[r0];
    const int n0  = rowptr[r0 + 1];
    int e1        = n0;                       // rowptr[r1]
    const int n1  = (r1 < N) ? rowptr[r1 + 1] : n0;

    const __half* __restrict__ X = g_nodefeat_h;
    const int foff = 2 * lane;
    float ax0 = 0.f, ay0 = 0.f, ax1 = 0.f, ay1 = 0.f;

    // main loop: 2 edges from each row per iteration
    for (; e0 + 2 <= n0 && e1 + 2 <= n1; e0 += 2, e1 += 2) {
        const int sA = colind[e0],     sB = colind[e0 + 1];
        const int sC = colind[e1],     sD = colind[e1 + 1];
        const uint2 wA = g_gauss_h[e0],     wB = g_gauss_h[e0 + 1];
        const uint2 wC = g_gauss_h[e1],     wD = g_gauss_h[e1 + 1];
        agg_edge2(X + (size_t)sA * KF + foff, wA, ax0, ay0);
        agg_edge2(X + (size_t)sB * KF + foff, wB, ax0, ay0);
        agg_edge2(X + (size_t)sC * KF + foff, wC, ax1, ay1);
        agg_edge2(X + (size_t)sD * KF + foff, wD, ax1, ay1);
    }
    // drain row 0
    for (; e0 + 2 <= n0; e0 += 2) {
        const int sA = colind[e0], sB = colind[e0 + 1];
        const uint2 wA = g_gauss_h[e0], wB = g_gauss_h[e0 + 1];
        agg_edge2(X + (size_t)sA * KF + foff, wA, ax0, ay0);
        agg_edge2(X + (size_t)sB * KF + foff, wB, ax0, ay0);
    }
    if (e0 < n0)
        agg_edge2(X + (size_t)colind[e0] * KF + foff, g_gauss_h[e0], ax0, ay0);
    // drain row 1
    for (; e1 + 2 <= n1; e1 += 2) {
        const int sC = colind[e1], sD = colind[e1 + 1];
        const uint2 wC = g_gauss_h[e1], wD = g_gauss_h[e1 + 1];
        agg_edge2(X + (size_t)sC * KF + foff, wC, ax1, ay1);
        agg_edge2(X + (size_t)sD * KF + foff, wD, ax1, ay1);
    }
    if (e1 < n1)
        agg_edge2(X + (size_t)colind[e1] * KF + foff, g_gauss_h[e1], ax1, ay1);

    const float2 b = *(const float2*)(bias + foff);
    *(float2*)(out + (size_t)r0 * FDIM + foff) = make_float2(ax0 + b.x, ay0 + b.y);
    if (r1 < N)
        *(float2*)(out + (size_t)r1 * FDIM + foff) = make_float2(ax1 + b.x, ay1 + b.y);
}

// ---------------------------------------------------------------------------
extern "C" void kernel_launch(void* const* d_in, const int* in_sizes, int n_in,
                              void* d_out, int out_size)
{
    const int*   rowptr    = (const int*)d_in[0];
    const int*   colind    = (const int*)d_in[1];
    // d_in[2] colptr, d_in[3] rowind, d_in[4] permute: unused in forward math
    const float* feat      = (const float*)d_in[5];
    const float* pseudo    = (const float*)d_in[6];
    const float* W_fc      = (const float*)d_in[7];
    const float* mu        = (const float*)d_in[8];
    const float* inv_sigma = (const float*)d_in[9];
    const float* bias      = (const float*)d_in[10];
    float*       out       = (float*)d_out;

    const int N = in_sizes[0] - 1;   // 50000
    const int E = in_sizes[1];       // 800000

    __half* nodefeat = nullptr;
    cudaGetSymbolAddress((void**)&nodefeat, g_nodefeat_h);

    // P: fused prep (gauss weights + W fp16 conversion)
    {
        prep_kernel<<<(E + 255) / 256, 256>>>(W_fc, pseudo, mu, inv_sigma, E);
    }
    // A: dense projection feat @ W_fc^T -> g_nodefeat_h [N, 256] fp16
    {
        cudaFuncSetAttribute(gemm_mma_kernel,
                             cudaFuncAttributeMaxDynamicSharedMemorySize, GEMM_SMEM);
        dim3 grid((N + 127) / 128, KF / 128);
        gemm_mma_kernel<<<grid, 256, GEMM_SMEM>>>(feat, nodefeat, N);
    }
    // C: dual-row weighted gather + reduce + bias -> out [N, 64]
    {
        const int warps = (N + 1) / 2;
        const int warps_per_block = 2;
        const int blocks = (warps + warps_per_block - 1) / warps_per_block;
        agg_kernel<<<blocks, warps_per_block * 32>>>(rowptr, colind, bias, out, N);
    }
}

// round 16
// speedup vs baseline: 1.1024x; 1.1024x over previous
#include <cuda_runtime.h>
#include <cuda_bf16.h>
#include <cuda_fp16.h>
#include <cstdint>

// Problem shape (fixed for this dataset variant)
#define NNODES 50000
#define NEDGES 800000
#define IN_DIM 256
#define KHEADS 4
#define FDIM   64
#define KF     256   // KHEADS * FDIM == IN_DIM here

// Scratch (device globals: allocation-free per harness rules)
__device__ __half  g_nodefeat_h[(size_t)NNODES * KF];  // [N, 256] fp16
__device__ uint2   g_gauss_h[NEDGES];                  // [E, 4] fp16 weights
__device__ __half  g_w_h[KF * IN_DIM];                 // W fp16

// ===========================================================================
// Helpers (family-common PTX only: ldmatrix + mma.sync, no tcgen05)
// ===========================================================================
__device__ __forceinline__ uint32_t smem_to_u32(const void* p) {
    uint32_t a;
    asm("{ .reg .u64 t; cvta.to.shared.u64 t, %1; cvt.u32.u64 %0, t; }"
        : "=r"(a) : "l"(p));
    return a;
}

__device__ __forceinline__ void ldmatrix_x4(uint32_t* r, uint32_t addr) {
    asm volatile("ldmatrix.sync.aligned.m8n8.x4.shared.b16 {%0,%1,%2,%3}, [%4];"
        : "=r"(r[0]), "=r"(r[1]), "=r"(r[2]), "=r"(r[3]) : "r"(addr));
}

__device__ __forceinline__ void mma_f16(float* d, const uint32_t* a,
                                        uint32_t b0, uint32_t b1) {
    asm volatile(
        "mma.sync.aligned.m16n8k16.row.col.f32.f16.f16.f32 "
        "{%0,%1,%2,%3}, {%4,%5,%6,%7}, {%8,%9}, {%0,%1,%2,%3};"
        : "+f"(d[0]), "+f"(d[1]), "+f"(d[2]), "+f"(d[3])
        : "r"(a[0]), "r"(a[1]), "r"(a[2]), "r"(a[3]), "r"(b0), "r"(b1));
}

__device__ __forceinline__ uint32_t pack2h(__half x, __half y) {
    uint16_t lo = *(uint16_t*)&x, hi = *(uint16_t*)&y;
    return (uint32_t)lo | ((uint32_t)hi << 16);
}

// ===========================================================================
// Kernel P: fused prep — gaussian weights for all edges + W fp32->fp16.
// (measured 7.7us vs 7.9 + 4.1 for the separate launches)
// ===========================================================================
__global__ void prep_kernel(const float* __restrict__ W,
                            const float* __restrict__ pseudo,
                            const float* __restrict__ mu,
                            const float* __restrict__ inv_sigma,
                            int E)
{
    const int i = blockIdx.x * blockDim.x + threadIdx.x;

    // W conversion: first 16384 threads, 1 float4 each
    if (i < (KF * IN_DIM) / 4) {
        const float4 v = ((const float4*)W)[i];
        ((uint2*)g_w_h)[i] = make_uint2(
            pack2h(__float2half_rn(v.x), __float2half_rn(v.y)),
            pack2h(__float2half_rn(v.z), __float2half_rn(v.w)));
    }

    // gaussian weights: one edge per thread
    if (i < E) {
        const float2 p = *(const float2*)(pseudo + 2 * (size_t)i);
        float w[4];
#pragma unroll
        for (int k = 0; k < 4; k++) {
            const float dx = p.x - mu[2 * k + 0];
            const float dy = p.y - mu[2 * k + 1];
            const float sx = inv_sigma[2 * k + 0];
            const float sy = inv_sigma[2 * k + 1];
            const float t  = dx * dx * sx * sx + dy * dy * sy * sy;
            w[k] = expf(-0.5f * t);
        }
        g_gauss_h[i] = make_uint2(
            pack2h(__float2half_rn(w[0]), __float2half_rn(w[1])),
            pack2h(__float2half_rn(w[2]), __float2half_rn(w[3])));
    }
}

// ===========================================================================
// Kernel A: fp16 tensor-core GEMM, software-pipelined (exact R12/R13 version).
// ===========================================================================
#define BK2     32
#define A_ROW_B 80                      // 32 fp16 + 8 pad (bytes)
#define A_BUF_B (128 * A_ROW_B)         // 10240
#define W_ROW_B 528                     // 256 fp16 + 8 pad (bytes)
#define W_BUF_B (128 * W_ROW_B)         // 67584
#define GEMM_SMEM (2 * A_BUF_B + W_BUF_B)   // 88064

__global__ __launch_bounds__(256, 2)
void gemm_mma_kernel(const float* __restrict__ A, __half* __restrict__ C, int M)
{
    extern __shared__ char smem[];
    const uint32_t sb  = smem_to_u32(smem);
    const uint32_t sW  = sb + 2 * A_BUF_B;

    const int tid  = threadIdx.x;
    const int wid  = tid >> 5;
    const int lane = tid & 31;
    const int m0   = blockIdx.x * 128;
    const int bn   = blockIdx.y * 128;

    const int wm = wid & 1;      // m half (64)
    const int wn = wid >> 1;     // n quarter (32)

    // ---- prologue: W tile 128x256 fp16 -> smem (once) ----
#pragma unroll
    for (int j = 0; j < 16; j++) {
        const int id  = tid + j * 256;     // 0..4095
        const int row = id >> 5;           // 0..127
        const int c8  = (id & 31) * 8;     // fp16 col
        const uint4 w = *(const uint4*)(g_w_h + (size_t)(bn + row) * IN_DIM + c8);
        *(uint4*)(smem + 2 * A_BUF_B + row * W_ROW_B + c8 * 2) = w;
    }

    float acc[4][4][4];
#pragma unroll
    for (int i = 0; i < 4; i++)
#pragma unroll
        for (int j = 0; j < 4; j++)
#pragma unroll
            for (int q = 0; q < 4; q++) acc[i][j][q] = 0.0f;

    float4 pref[4];
#pragma unroll
    for (int j = 0; j < 4; j++) {               // prefetch chunk 0
        const int id  = tid + j * 256;
        const int row = id >> 3;
        const int c4  = (id & 7) * 4;
        const int gm  = m0 + row;
        pref[j] = (gm < M)
            ? *(const float4*)(A + (size_t)gm * IN_DIM + 0 * BK2 + c4)
            : make_float4(0.f, 0.f, 0.f, 0.f);
    }

    for (int c = 0; c < IN_DIM / BK2; c++) {
        const uint32_t abuf = sb + (uint32_t)(c & 1) * A_BUF_B;

        // ---- STS chunk c (convert fp32 regs -> fp16 smem) ----
#pragma unroll
        for (int j = 0; j < 4; j++) {
            const int id  = tid + j * 256;
            const int row = id >> 3;
            const int c4  = (id & 7) * 4;
            const float4 a = pref[j];
            asm volatile("st.shared.v2.b32 [%0], {%1,%2};" ::
                "r"(abuf + (uint32_t)(row * A_ROW_B + c4 * 2)),
                "r"(pack2h(__float2half_rn(a.x), __float2half_rn(a.y))),
                "r"(pack2h(__float2half_rn(a.z), __float2half_rn(a.w))) : "memory");
        }
        // ---- prefetch chunk c+1 (overlaps with compute below) ----
        if (c < IN_DIM / BK2 - 1) {
#pragma unroll
            for (int j = 0; j < 4; j++) {
                const int id  = tid + j * 256;
                const int row = id >> 3;
                const int c4  = (id & 7) * 4;
                const int gm  = m0 + row;
                pref[j] = (gm < M)
                    ? *(const float4*)(A + (size_t)gm * IN_DIM + (c + 1) * BK2 + c4)
                    : make_float4(0.f, 0.f, 0.f, 0.f);
            }
        }
        __syncthreads();

        // ---- compute chunk c: 2 k16 steps ----
#pragma unroll
        for (int ks = 0; ks < 2; ks++) {
            const uint32_t kbyte = (uint32_t)((ks * 16 + (lane >> 4) * 8) * 2);

            uint32_t af[4][4];
#pragma unroll
            for (int mt = 0; mt < 4; mt++) {
                const uint32_t roff =
                    (uint32_t)((wm * 64 + mt * 16 + (lane & 15)) * A_ROW_B) + kbyte;
                ldmatrix_x4(af[mt], abuf + roff);
            }
            uint32_t bf[2][4];
            const uint32_t wkoff = (uint32_t)(c * BK2 * 2) + kbyte;
#pragma unroll
            for (int bg = 0; bg < 2; bg++) {
                const uint32_t roff =
                    (uint32_t)((wn * 32 + bg * 16 + (lane & 15)) * W_ROW_B) + wkoff;
                ldmatrix_x4(bf[bg], sW + roff);
            }

#pragma unroll
            for (int mt = 0; mt < 4; mt++) {
#pragma unroll
                for (int nt = 0; nt < 4; nt++) {
                    const int bg = nt >> 1, sel = nt & 1;
                    mma_f16(acc[mt][nt], af[mt], bf[bg][sel], bf[bg][sel + 2]);
                }
            }
        }
    }

    // ---- epilogue: fragment -> gmem fp16 ----
    const int qrow = lane >> 2;
    const int qcol = (lane & 3) * 2;
#pragma unroll
    for (int mt = 0; mt < 4; mt++) {
        const int r0 = m0 + wm * 64 + mt * 16 + qrow;
#pragma unroll
        for (int nt = 0; nt < 4; nt++) {
            const int col = bn + wn * 32 + nt * 8 + qcol;
            if (r0 < M)
                *(__half2*)(C + (size_t)r0 * KF + col) =
                    __floats2half2_rn(acc[mt][nt][0], acc[mt][nt][1]);
            if (r0 + 8 < M)
                *(__half2*)(C + (size_t)(r0 + 8) * KF + col) =
                    __floats2half2_rn(acc[mt][nt][2], acc[mt][nt][3]);
        }
    }
}

// ---------------------------------------------------------------------------
// Kernel C: CSR row-parallel weighted gather + reduce. One warp per row.
// (exact R13 version — best measured agg; fp16 weights, 2-warp blocks)
// ---------------------------------------------------------------------------
__global__ void agg_kernel(const int* __restrict__ rowptr,
                           const int* __restrict__ colind,
                           const float* __restrict__ bias,
                           float* __restrict__ out, int N)
{
    const int warp = (blockIdx.x * blockDim.x + threadIdx.x) >> 5;
    const int lane = threadIdx.x & 31;
    if (warp >= N) return;

    const int e0 = rowptr[warp];
    const int e1 = rowptr[warp + 1];

    float ax = 0.f, ay = 0.f;
    const __half* __restrict__ X = g_nodefeat_h;
    const int foff = 2 * lane;

    int e = e0;
    for (; e + 2 <= e1; e += 2) {
        const int s0 = colind[e];
        const int s1 = colind[e + 1];
        const uint2 wp0 = g_gauss_h[e];
        const uint2 wp1 = g_gauss_h[e + 1];
        const __half* b0 = X + (size_t)s0 * KF + foff;
        const __half* b1 = X + (size_t)s1 * KF + foff;
        const float2 v00 = __half22float2(*(const __half2*)(b0 + 0));
        const float2 v01 = __half22float2(*(const __half2*)(b0 + 64));
        const float2 v02 = __half22float2(*(const __half2*)(b0 + 128));
        const float2 v03 = __half22float2(*(const __half2*)(b0 + 192));
        const float2 v10 = __half22float2(*(const __half2*)(b1 + 0));
        const float2 v11 = __half22float2(*(const __half2*)(b1 + 64));
        const float2 v12 = __half22float2(*(const __half2*)(b1 + 128));
        const float2 v13 = __half22float2(*(const __half2*)(b1 + 192));
        const float2 w0a = __half22float2(*(const __half2*)&wp0.x);
        const float2 w0b = __half22float2(*(const __half2*)&wp0.y);
        const float2 w1a = __half22float2(*(const __half2*)&wp1.x);
        const float2 w1b = __half22float2(*(const __half2*)&wp1.y);
        ax = fmaf(w0a.x, v00.x, ax); ay = fmaf(w0a.x, v00.y, ay);
        ax = fmaf(w0a.y, v01.x, ax); ay = fmaf(w0a.y, v01.y, ay);
        ax = fmaf(w0b.x, v02.x, ax); ay = fmaf(w0b.x, v02.y, ay);
        ax = fmaf(w0b.y, v03.x, ax); ay = fmaf(w0b.y, v03.y, ay);
        ax = fmaf(w1a.x, v10.x, ax); ay = fmaf(w1a.x, v10.y, ay);
        ax = fmaf(w1a.y, v11.x, ax); ay = fmaf(w1a.y, v11.y, ay);
        ax = fmaf(w1b.x, v12.x, ax); ay = fmaf(w1b.x, v12.y, ay);
        ax = fmaf(w1b.y, v13.x, ax); ay = fmaf(w1b.y, v13.y, ay);
    }
    if (e < e1) {
        const int s0 = colind[e];
        const uint2 wp0 = g_gauss_h[e];
        const __half* b0 = X + (size_t)s0 * KF + foff;
        const float2 v00 = __half22float2(*(const __half2*)(b0 + 0));
        const float2 v01 = __half22float2(*(const __half2*)(b0 + 64));
        const float2 v02 = __half22float2(*(const __half2*)(b0 + 128));
        const float2 v03 = __half22float2(*(const __half2*)(b0 + 192));
        const float2 w0a = __half22float2(*(const __half2*)&wp0.x);
        const float2 w0b = __half22float2(*(const __half2*)&wp0.y);
        ax = fmaf(w0a.x, v00.x, ax); ay = fmaf(w0a.x, v00.y, ay);
        ax = fmaf(w0a.y, v01.x, ax); ay = fmaf(w0a.y, v01.y, ay);
        ax = fmaf(w0b.x, v02.x, ax); ay = fmaf(w0b.x, v02.y, ay);
        ax = fmaf(w0b.y, v03.x, ax); ay = fmaf(w0b.y, v03.y, ay);
    }

    const float2 b = *(const float2*)(bias + foff);
    *(float2*)(out + (size_t)warp * FDIM + foff) = make_float2(ax + b.x, ay + b.y);
}

// ---------------------------------------------------------------------------
extern "C" void kernel_launch(void* const* d_in, const int* in_sizes, int n_in,
                              void* d_out, int out_size)
{
    const int*   rowptr    = (const int*)d_in[0];
    const int*   colind    = (const int*)d_in[1];
    // d_in[2] colptr, d_in[3] rowind, d_in[4] permute: unused in forward math
    const float* feat      = (const float*)d_in[5];
    const float* pseudo    = (const float*)d_in[6];
    const float* W_fc      = (const float*)d_in[7];
    const float* mu        = (const float*)d_in[8];
    const float* inv_sigma = (const float*)d_in[9];
    const float* bias      = (const float*)d_in[10];
    float*       out       = (float*)d_out;

    const int N = in_sizes[0] - 1;   // 50000
    const int E = in_sizes[1];       // 800000

    __half* nodefeat = nullptr;
    cudaGetSymbolAddress((void**)&nodefeat, g_nodefeat_h);

    // P: fused prep (gauss weights + W fp16 conversion)
    {
        prep_kernel<<<(E + 255) / 256, 256>>>(W_fc, pseudo, mu, inv_sigma, E);
    }
    // A: dense projection feat @ W_fc^T -> g_nodefeat_h [N, 256] fp16
    {
        cudaFuncSetAttribute(gemm_mma_kernel,
                             cudaFuncAttributeMaxDynamicSharedMemorySize, GEMM_SMEM);
        dim3 grid((N + 127) / 128, KF / 128);
        gemm_mma_kernel<<<grid, 256, GEMM_SMEM>>>(feat, nodefeat, N);
    }
    // C: row-parallel weighted gather + reduce + bias -> out [N, 64]
    {
        const int warps_per_block = 2;
        const int blocks = (N + warps_per_block - 1) / warps_per_block;
        agg_kernel<<<blocks, warps_per_block * 32>>>(rowptr, colind, bias, out, N);
    }
}